// round 14
// baseline (speedup 1.0000x reference)
#include <cuda_runtime.h>
#include <stdint.h>
#include <math.h>

#define B_ROWS 131072
#define PTS 8
#define XCOLS 17
#define HID 256
#define NBINS 32
#define OUTC 520
#define BN_EPS 1e-5f

// ---------------- static device scratch ----------------
__device__ float g_h2[(size_t)B_ROWS * HID];
__device__ float g_Z [(size_t)B_ROWS * OUTC];
__device__ float g_mom[44 * 128];
__device__ float g_ps2[HID * 1024];
__device__ float g_pq2[HID * 1024];
__device__ float g_W1p[PTS * HID];
__device__ float g_c1[HID];
__device__ float g_a2[HID], g_cs2[HID];

// ---------------- packed f32x2 helpers ----------------
#define FMA2(C, A, B) \
    asm("fma.rn.f32x2 %0, %1, %2, %0;" : "+l"(C) : "l"(A), "l"(B))
#define PACK2(P, F) \
    asm("mov.b64 %0, {%1, %1};" : "=l"(P) : "r"(__float_as_uint(F)))
#define UNPK(C, F0, F1) { \
    F0 = __uint_as_float((unsigned)(C)); \
    F1 = __uint_as_float((unsigned)((C) >> 32)); }

__host__ __device__ __forceinline__ int triidx(int p, int q) {
    return p * 8 - (p * (p - 1)) / 2 + (q - p);
}

// ---------------- moments of x[:, :8]: 8 sums + 36 cross sums ----------------
__global__ void k_stats_x2(const float* __restrict__ x) {
    __shared__ float wred[8][44];
    int t = threadIdx.x;
    int lane = t & 31, w = t >> 5;
    long base = (long)blockIdx.x * 1024;
    float s1[8], s2[36];
    #pragma unroll
    for (int p = 0; p < 8; p++) s1[p] = 0.f;
    #pragma unroll
    for (int i = 0; i < 36; i++) s2[i] = 0.f;
    for (int r = t; r < 1024; r += 256) {
        const float* xp = &x[(base + r) * XCOLS];
        float v[8];
        #pragma unroll
        for (int p = 0; p < 8; p++) v[p] = xp[p];
        #pragma unroll
        for (int p = 0; p < 8; p++) s1[p] += v[p];
        #pragma unroll
        for (int p = 0; p < 8; p++)
            #pragma unroll
            for (int q = p; q < 8; q++)
                s2[triidx(p, q)] += v[p] * v[q];
    }
    #pragma unroll
    for (int i = 0; i < 8; i++) {
        float v = s1[i];
        #pragma unroll
        for (int o = 16; o > 0; o >>= 1) v += __shfl_xor_sync(0xFFFFFFFFu, v, o);
        if (lane == 0) wred[w][i] = v;
    }
    #pragma unroll
    for (int i = 0; i < 36; i++) {
        float v = s2[i];
        #pragma unroll
        for (int o = 16; o > 0; o >>= 1) v += __shfl_xor_sync(0xFFFFFFFFu, v, o);
        if (lane == 0) wred[w][8 + i] = v;
    }
    __syncthreads();
    if (t < 44) {
        float S = 0.f;
        #pragma unroll
        for (int j = 0; j < 8; j++) S += wred[j][t];
        g_mom[t * 128 + blockIdx.x] = S;
    }
}

// ---------------- finalize bn0 + analytic bn1, fold into Wg/cg ----------------
__global__ void k_prep1(const float* __restrict__ g0, const float* __restrict__ b0,
                        const float* __restrict__ w1,
                        const float* __restrict__ g1, const float* __restrict__ b1) {
    __shared__ double mom[44];
    __shared__ double a0s[8], cs0s[8];
    __shared__ double m2s[8][8];
    int t = threadIdx.x;
    if (t < 44) {
        double S = 0.0;
        for (int j = 0; j < 128; j++) S += (double)g_mom[t * 128 + j];
        mom[t] = S / (double)B_ROWS;
    }
    __syncthreads();
    if (t < 8) {
        double m = mom[t];
        double v = mom[8 + triidx(t, t)] - m * m;
        double a = (double)g0[t] / sqrt(v + (double)BN_EPS);
        a0s[t] = a;
        cs0s[t] = (double)b0[t] - m * a;
    }
    if (t >= 64 && t < 128) {
        int p = (t - 64) >> 3, q = (t - 64) & 7;
        int pl = p < q ? p : q, qh = p < q ? q : p;
        m2s[p][q] = mom[8 + triidx(pl, qh)];
    }
    __syncthreads();
    int j = t;
    double Wf[8];
    double c1f = 0.0;
    #pragma unroll
    for (int p = 0; p < 8; p++) {
        double w = (double)w1[p * HID + j];
        Wf[p] = w * a0s[p];
        c1f += cs0s[p] * w;
    }
    double mx = 0.0;
    #pragma unroll
    for (int p = 0; p < 8; p++) mx += mom[p] * Wf[p];
    double mean1 = mx + c1f;
    double eh2 = c1f * c1f + 2.0 * c1f * mx;
    #pragma unroll
    for (int p = 0; p < 8; p++)
        #pragma unroll
        for (int q = 0; q < 8; q++)
            eh2 += m2s[p][q] * Wf[p] * Wf[q];
    double var1 = eh2 - mean1 * mean1;
    double a1 = (double)g1[j] / sqrt(var1 + (double)BN_EPS);
    double cs1 = (double)b1[j] - mean1 * a1;
    #pragma unroll
    for (int p = 0; p < 8; p++) g_W1p[p * HID + j] = (float)(Wf[p] * a1);
    g_c1[j] = (float)(c1f * a1 + cs1);
}

// ---------------- BN2 stats finalize ----------------
__global__ void k_bnstats(const float* __restrict__ g, const float* __restrict__ b) {
    __shared__ float ss[256], sq[256];
    int t = threadIdx.x, c = blockIdx.x;
    float S = 0.f, Q = 0.f;
    for (int j = t; j < 1024; j += 256) { S += g_ps2[c * 1024 + j]; Q += g_pq2[c * 1024 + j]; }
    ss[t] = S; sq[t] = Q;
    __syncthreads();
    for (int o = 128; o > 0; o >>= 1) {
        if (t < o) { ss[t] += ss[t + o]; sq[t] += sq[t + o]; }
        __syncthreads();
    }
    if (t == 0) {
        float m = ss[0] / (float)B_ROWS;
        float v = sq[0] / (float)B_ROWS - m * m;
        float a = g[c] * rsqrtf(v + BN_EPS);
        g_a2[c] = a; g_cs2[c] = b[c] - m * a;
    }
}

// ---------------- shared GEMM machinery (f32x2) ----------------
#define DECL_ROW(I) unsigned long long c##I##0 = 0ull, c##I##1 = 0ull, c##I##2 = 0ull, c##I##3 = 0ull;

#define ROWFMA(I, AF) { \
    unsigned long long pa; \
    PACK2(pa, AF); \
    FMA2(c##I##0, pa, pb0); \
    FMA2(c##I##1, pa, pb1); \
    FMA2(c##I##2, pa, pb2); \
    FMA2(c##I##3, pa, pb3); }

#define KSTEP(KK) { \
    float4 a0 = *(const float4*)&As[KK][ty * 8]; \
    float4 a1 = *(const float4*)&As[KK][ty * 8 + 4]; \
    ulonglong2 bA = *(const ulonglong2*)&Bs[KK][tx * 8]; \
    ulonglong2 bB = *(const ulonglong2*)&Bs[KK][tx * 8 + 4]; \
    unsigned long long pb0 = bA.x, pb1 = bA.y, pb2 = bB.x, pb3 = bB.y; \
    ROWFMA(0, a0.x) ROWFMA(1, a0.y) ROWFMA(2, a0.z) ROWFMA(3, a0.w) \
    ROWFMA(4, a1.x) ROWFMA(5, a1.y) ROWFMA(6, a1.z) ROWFMA(7, a1.w) }

// ---------------- GEMM2: h2 = relu(Wg-dot(x)+cg) @ w2, bn2 partials ----------------
#define ROW2(I) { \
    float f0, f1, f2, f3, f4, f5, f6, f7; \
    UNPK(c##I##0, f0, f1) UNPK(c##I##1, f2, f3) UNPK(c##I##2, f4, f5) UNPK(c##I##3, f6, f7) \
    long r = row0 + ty * 8 + I; \
    *(float4*)&g_h2[r * HID + col0 + tx * 8]     = make_float4(f0, f1, f2, f3); \
    *(float4*)&g_h2[r * HID + col0 + tx * 8 + 4] = make_float4(f4, f5, f6, f7); \
    s0 += f0; s1 += f1; s2 += f2; s3 += f3; s4 += f4; s5 += f5; s6 += f6; s7 += f7; \
    q0 += f0*f0; q1 += f1*f1; q2 += f2*f2; q3 += f3*f3; \
    q4 += f4*f4; q5 += f5*f5; q6 += f6*f6; q7 += f7*f7; }

__global__ void __launch_bounds__(256) k_gemm2(const float* __restrict__ w2, const float* __restrict__ x) {
    __shared__ __align__(16) float As[8][132];
    __shared__ __align__(16) float Bs[8][132];
    __shared__ __align__(16) float xs[128][8];
    __shared__ __align__(16) float Wgs[8][HID];
    __shared__ __align__(16) float cgs[HID];
    __shared__ float red[16][128];
    int t = threadIdx.x;
    int tx = t & 15, ty = t >> 4;
    long row0 = (long)blockIdx.y * 128;
    int col0 = blockIdx.x * 128;
    for (int e = t; e < 1024; e += 256) {
        int r = e >> 3, p = e & 7;
        xs[r][p] = x[(row0 + r) * XCOLS + p];
    }
    for (int e = t; e < 2048; e += 256) Wgs[e >> 8][e & 255] = g_W1p[e];
    cgs[t] = g_c1[t];
    DECL_ROW(0) DECL_ROW(1) DECL_ROW(2) DECL_ROW(3)
    DECL_ROW(4) DECL_ROW(5) DECL_ROW(6) DECL_ROW(7)
    int bc = t & 127, bk = t >> 7;
    int kp = (t & 3) * 2, cr = t >> 2;
    __syncthreads();
    for (int k0 = 0; k0 < 256; k0 += 8) {
        #pragma unroll
        for (int i = 0; i < 2; i++) {
            int r = cr + i * 64;
            unsigned long long acc = *(const unsigned long long*)&cgs[k0 + kp];
            #pragma unroll
            for (int p = 0; p < 8; p++) {
                unsigned long long wv = *(const unsigned long long*)&Wgs[p][k0 + kp];
                unsigned long long xv;
                PACK2(xv, xs[r][p]);
                FMA2(acc, xv, wv);
            }
            float f0, f1;
            UNPK(acc, f0, f1)
            As[kp][r]     = fmaxf(f0, 0.f);
            As[kp + 1][r] = fmaxf(f1, 0.f);
        }
        #pragma unroll
        for (int i = 0; i < 4; i++) {
            int k = bk + i * 2;
            Bs[k][bc] = w2[(k0 + k) * HID + col0 + bc];
        }
        __syncthreads();
        #pragma unroll
        for (int k = 0; k < 8; k++) KSTEP(k)
        __syncthreads();
    }
    float s0 = 0.f, s1 = 0.f, s2 = 0.f, s3 = 0.f, s4 = 0.f, s5 = 0.f, s6 = 0.f, s7 = 0.f;
    float q0 = 0.f, q1 = 0.f, q2 = 0.f, q3 = 0.f, q4 = 0.f, q5 = 0.f, q6 = 0.f, q7 = 0.f;
    ROW2(0) ROW2(1) ROW2(2) ROW2(3) ROW2(4) ROW2(5) ROW2(6) ROW2(7)
    red[ty][tx * 8 + 0] = s0; red[ty][tx * 8 + 1] = s1;
    red[ty][tx * 8 + 2] = s2; red[ty][tx * 8 + 3] = s3;
    red[ty][tx * 8 + 4] = s4; red[ty][tx * 8 + 5] = s5;
    red[ty][tx * 8 + 6] = s6; red[ty][tx * 8 + 7] = s7;
    __syncthreads();
    if (t < 128) {
        float S = 0.f;
        #pragma unroll
        for (int y = 0; y < 16; y++) S += red[y][t];
        g_ps2[(long)(col0 + t) * 1024 + blockIdx.y] = S;
    }
    __syncthreads();
    red[ty][tx * 8 + 0] = q0; red[ty][tx * 8 + 1] = q1;
    red[ty][tx * 8 + 2] = q2; red[ty][tx * 8 + 3] = q3;
    red[ty][tx * 8 + 4] = q4; red[ty][tx * 8 + 5] = q5;
    red[ty][tx * 8 + 6] = q6; red[ty][tx * 8 + 7] = q7;
    __syncthreads();
    if (t < 128) {
        float Q = 0.f;
        #pragma unroll
        for (int y = 0; y < 16; y++) Q += red[y][t];
        g_pq2[(long)(col0 + t) * 1024 + blockIdx.y] = Q;
    }
}

// ---------------- GEMM3 merged: bx<4 main 128 cols, bx==4 remainder 8 cols ----------------
#define ROW3(I) { \
    float f0, f1, f2, f3, f4, f5, f6, f7; \
    UNPK(c##I##0, f0, f1) UNPK(c##I##1, f2, f3) UNPK(c##I##2, f4, f5) UNPK(c##I##3, f6, f7) \
    long r = row0 + ty * 8 + I; \
    *(float4*)&g_Z[r * OUTC + c0]     = make_float4(f0 + bb0.x, f1 + bb0.y, f2 + bb0.z, f3 + bb0.w); \
    *(float4*)&g_Z[r * OUTC + c0 + 4] = make_float4(f4 + bb1.x, f5 + bb1.y, f6 + bb1.z, f7 + bb1.w); }

__global__ void __launch_bounds__(256) k_gemm3(const float* __restrict__ w3, const float* __restrict__ b3) {
    __shared__ __align__(16) float As[8][132];
    __shared__ __align__(16) float Bs[8][132];
    __shared__ float Ws[256][8];
    __shared__ float a2s[HID], cs2s[HID];
    int t = threadIdx.x;
    long row0 = (long)blockIdx.y * 128;
    a2s[t]  = g_a2[t];
    cs2s[t] = g_cs2[t];
    int ar = t >> 3, ak = t & 7;

    if (blockIdx.x < 4) {
        int tx = t & 15, ty = t >> 4;
        int col0 = blockIdx.x * 128;
        DECL_ROW(0) DECL_ROW(1) DECL_ROW(2) DECL_ROW(3)
        DECL_ROW(4) DECL_ROW(5) DECL_ROW(6) DECL_ROW(7)
        int bc = t & 127, bk = t >> 7;
        __syncthreads();
        for (int k0 = 0; k0 < 256; k0 += 8) {
            #pragma unroll
            for (int i = 0; i < 4; i++) {
                int r = ar + i * 32;
                float h = g_h2[(row0 + r) * HID + k0 + ak];
                As[ak][r] = fmaxf(a2s[k0 + ak] * h + cs2s[k0 + ak], 0.f);
            }
            #pragma unroll
            for (int i = 0; i < 4; i++) {
                int k = bk + i * 2;
                Bs[k][bc] = w3[(long)(k0 + k) * OUTC + col0 + bc];
            }
            __syncthreads();
            #pragma unroll
            for (int k = 0; k < 8; k++) KSTEP(k)
            __syncthreads();
        }
        int c0 = col0 + tx * 8;
        float4 bb0 = *(const float4*)&b3[c0];
        float4 bb1 = *(const float4*)&b3[c0 + 4];
        ROW3(0) ROW3(1) ROW3(2) ROW3(3) ROW3(4) ROW3(5) ROW3(6) ROW3(7)
    } else {
        #pragma unroll
        for (int e = 0; e < 8; e++) {
            int idx = t + e * 256;
            int k = idx >> 3, c = idx & 7;
            Ws[k][c] = w3[(long)k * OUTC + 512 + c];
        }
        __syncthreads();
        int c = t & 7, rg = t >> 3;
        float bb = b3[512 + c];
        float ac0 = bb, ac1 = bb, ac2 = bb, ac3 = bb;
        for (int k0 = 0; k0 < 256; k0 += 8) {
            if (k0) __syncthreads();
            #pragma unroll
            for (int i = 0; i < 4; i++) {
                int r = ar + i * 32;
                float h = g_h2[(row0 + r) * HID + k0 + ak];
                As[ak][r] = fmaxf(a2s[k0 + ak] * h + cs2s[k0 + ak], 0.f);
            }
            __syncthreads();
            #pragma unroll
            for (int kk = 0; kk < 8; kk++) {
                float w = Ws[k0 + kk][c];
                float4 av = *(const float4*)&As[kk][rg * 4];
                ac0 += av.x * w;
                ac1 += av.y * w;
                ac2 += av.z * w;
                ac3 += av.w * w;
            }
        }
        long r = row0 + rg * 4;
        g_Z[r * OUTC + 512 + c]       = ac0;
        g_Z[(r + 1) * OUTC + 512 + c] = ac1;
        g_Z[(r + 2) * OUTC + 512 + c] = ac2;
        g_Z[(r + 3) * OUTC + 512 + c] = ac3;
    }
}

// ---------------- spline ----------------
__global__ void __launch_bounds__(128) k_spline(const float* __restrict__ x, float* __restrict__ out) {
    __shared__ float Zs[16 * OUTC];
    __shared__ float jf[16][8];
    int t = threadIdx.x;
    long row0 = (long)blockIdx.x * 16;
    for (int e = t; e < 16 * OUTC; e += 128) Zs[e] = g_Z[row0 * OUTC + e];
    __syncthreads();
    int r = t >> 3, tt = t & 7;
    long row = row0 + r;
    const float* z = &Zs[r * OUTC + tt * 65];

    float V[33], W[32];
    float Wn = 0.f;
    #pragma unroll
    for (int k = 0; k < 32; k++) { W[k] = __expf(z[33 + k]); Wn += W[k]; }
    #pragma unroll
    for (int k = 0; k < 33; k++) V[k] = __expf(z[k]);
    float Ttz = 0.f;
    #pragma unroll
    for (int k = 0; k < 32; k++) Ttz += (V[k] + V[k + 1]) * 0.5f * W[k];

    float xB = fminf(x[row * XCOLS + 8 + tt], 1.f - 1e-6f);
    float invWn = 1.f / Wn;

    float cw = 0.f, cvw = 0.f;
    float pre = 0.f, preV = 0.f;
    float Wj = W[31], Vj = V[31], Vj1 = V[32];
    bool found = false;
    #pragma unroll
    for (int k = 0; k < 32; k++) {
        float nw = cw + W[k];
        float post = nw * invWn;
        if (!found && post > xB) {
            found = true;
            pre = cw; preV = cvw;
            Wj = W[k]; Vj = V[k]; Vj1 = V[k + 1];
        }
        cw = nw;
        cvw += (V[k] + V[k + 1]) * 0.5f * W[k];
    }
    if (!found) {
        pre  = cw  - W[31];
        preV = cvw - (V[31] + V[32]) * 0.5f * W[31];
    }

    float invT  = 1.f / Ttz;
    float alpha = (xB * Wn - pre) / Wj;
    float shift = preV * invT;
    float VjN  = Vj  * Wn * invT;
    float Vj1N = Vj1 * Wn * invT;
    float WjN  = Wj * invWn;
    float yB = (0.5f * alpha * alpha * (Vj1N - VjN) + alpha * VjN) * WjN + shift;

    out[row * XCOLS + 8 + tt] = yB;
    out[row * XCOLS + tt]     = x[row * XCOLS + tt];
    jf[r][tt] = VjN + alpha * (Vj1N - VjN);
    __syncthreads();
    if (tt == 0) {
        float jac = x[row * XCOLS + 16];
        #pragma unroll
        for (int q = 0; q < 8; q++) jac *= jf[r][q];
        out[row * XCOLS + 16] = jac;
    }
}

// ---------------- launch ----------------
extern "C" void kernel_launch(void* const* d_in, const int* in_sizes, int n_in,
                              void* d_out, int out_size) {
    const float* x   = (const float*)d_in[0];
    const float* g0  = (const float*)d_in[1];
    const float* b0  = (const float*)d_in[2];
    const float* w1  = (const float*)d_in[3];
    const float* g1  = (const float*)d_in[4];
    const float* b1  = (const float*)d_in[5];
    const float* w2  = (const float*)d_in[6];
    const float* g2  = (const float*)d_in[7];
    const float* b2  = (const float*)d_in[8];
    const float* w3  = (const float*)d_in[9];
    const float* b3  = (const float*)d_in[10];
    float* out = (float*)d_out;

    k_stats_x2<<<128, 256>>>(x);
    k_prep1<<<1, 256>>>(g0, b0, w1, g1, b1);
    k_gemm2<<<dim3(2, 1024), 256>>>(w2, x);
    k_bnstats<<<256, 256>>>(g2, b2);
    k_gemm3<<<dim3(5, 1024), 256>>>(w3, b3);
    k_spline<<<8192, 128>>>(x, out);
}

// round 15
// speedup vs baseline: 1.0085x; 1.0085x over previous
#include <cuda_runtime.h>
#include <stdint.h>
#include <math.h>

#define B_ROWS 131072
#define PTS 8
#define XCOLS 17
#define HID 256
#define NBINS 32
#define OUTC 520
#define BN_EPS 1e-5f

// ---------------- static device scratch ----------------
__device__ float g_h2[(size_t)B_ROWS * HID];
__device__ float g_Z [(size_t)B_ROWS * OUTC];
__device__ float g_mom[44 * 128];
__device__ float g_ps2[HID * 1024];
__device__ float g_pq2[HID * 1024];
__device__ float g_W1p[PTS * HID];
__device__ float g_c1[HID];
__device__ float g_a2[HID], g_cs2[HID];

// ---------------- packed f32x2 helpers ----------------
#define FMA2(C, A, B) \
    asm("fma.rn.f32x2 %0, %1, %2, %0;" : "+l"(C) : "l"(A), "l"(B))
#define PACK2(P, F) \
    asm("mov.b64 %0, {%1, %1};" : "=l"(P) : "r"(__float_as_uint(F)))
#define UNPK(C, F0, F1) { \
    F0 = __uint_as_float((unsigned)(C)); \
    F1 = __uint_as_float((unsigned)((C) >> 32)); }

__host__ __device__ __forceinline__ int triidx(int p, int q) {
    return p * 8 - (p * (p - 1)) / 2 + (q - p);
}

// ---------------- moments of x[:, :8]: 8 sums + 36 cross sums ----------------
__global__ void k_stats_x2(const float* __restrict__ x) {
    __shared__ float wred[8][44];
    int t = threadIdx.x;
    int lane = t & 31, w = t >> 5;
    long base = (long)blockIdx.x * 1024;
    float s1[8], s2[36];
    #pragma unroll
    for (int p = 0; p < 8; p++) s1[p] = 0.f;
    #pragma unroll
    for (int i = 0; i < 36; i++) s2[i] = 0.f;
    for (int r = t; r < 1024; r += 256) {
        const float* xp = &x[(base + r) * XCOLS];
        float v[8];
        #pragma unroll
        for (int p = 0; p < 8; p++) v[p] = xp[p];
        #pragma unroll
        for (int p = 0; p < 8; p++) s1[p] += v[p];
        #pragma unroll
        for (int p = 0; p < 8; p++)
            #pragma unroll
            for (int q = p; q < 8; q++)
                s2[triidx(p, q)] += v[p] * v[q];
    }
    #pragma unroll
    for (int i = 0; i < 8; i++) {
        float v = s1[i];
        #pragma unroll
        for (int o = 16; o > 0; o >>= 1) v += __shfl_xor_sync(0xFFFFFFFFu, v, o);
        if (lane == 0) wred[w][i] = v;
    }
    #pragma unroll
    for (int i = 0; i < 36; i++) {
        float v = s2[i];
        #pragma unroll
        for (int o = 16; o > 0; o >>= 1) v += __shfl_xor_sync(0xFFFFFFFFu, v, o);
        if (lane == 0) wred[w][8 + i] = v;
    }
    __syncthreads();
    if (t < 44) {
        float S = 0.f;
        #pragma unroll
        for (int j = 0; j < 8; j++) S += wred[j][t];
        g_mom[t * 128 + blockIdx.x] = S;
    }
}

// ---------------- finalize bn0 + analytic bn1, fold into Wg/cg ----------------
__global__ void k_prep1(const float* __restrict__ g0, const float* __restrict__ b0,
                        const float* __restrict__ w1,
                        const float* __restrict__ g1, const float* __restrict__ b1) {
    __shared__ double mom[44];
    __shared__ double a0s[8], cs0s[8];
    __shared__ double m2s[8][8];
    int t = threadIdx.x;
    if (t < 44) {
        double S = 0.0;
        for (int j = 0; j < 128; j++) S += (double)g_mom[t * 128 + j];
        mom[t] = S / (double)B_ROWS;
    }
    __syncthreads();
    if (t < 8) {
        double m = mom[t];
        double v = mom[8 + triidx(t, t)] - m * m;
        double a = (double)g0[t] / sqrt(v + (double)BN_EPS);
        a0s[t] = a;
        cs0s[t] = (double)b0[t] - m * a;
    }
    if (t >= 64 && t < 128) {
        int p = (t - 64) >> 3, q = (t - 64) & 7;
        int pl = p < q ? p : q, qh = p < q ? q : p;
        m2s[p][q] = mom[8 + triidx(pl, qh)];
    }
    __syncthreads();
    int j = t;
    double Wf[8];
    double c1f = 0.0;
    #pragma unroll
    for (int p = 0; p < 8; p++) {
        double w = (double)w1[p * HID + j];
        Wf[p] = w * a0s[p];
        c1f += cs0s[p] * w;
    }
    double mx = 0.0;
    #pragma unroll
    for (int p = 0; p < 8; p++) mx += mom[p] * Wf[p];
    double mean1 = mx + c1f;
    double eh2 = c1f * c1f + 2.0 * c1f * mx;
    #pragma unroll
    for (int p = 0; p < 8; p++)
        #pragma unroll
        for (int q = 0; q < 8; q++)
            eh2 += m2s[p][q] * Wf[p] * Wf[q];
    double var1 = eh2 - mean1 * mean1;
    double a1 = (double)g1[j] / sqrt(var1 + (double)BN_EPS);
    double cs1 = (double)b1[j] - mean1 * a1;
    #pragma unroll
    for (int p = 0; p < 8; p++) g_W1p[p * HID + j] = (float)(Wf[p] * a1);
    g_c1[j] = (float)(c1f * a1 + cs1);
}

// ---------------- BN2 stats finalize ----------------
__global__ void k_bnstats(const float* __restrict__ g, const float* __restrict__ b) {
    __shared__ float ss[256], sq[256];
    int t = threadIdx.x, c = blockIdx.x;
    float S = 0.f, Q = 0.f;
    for (int j = t; j < 1024; j += 256) { S += g_ps2[c * 1024 + j]; Q += g_pq2[c * 1024 + j]; }
    ss[t] = S; sq[t] = Q;
    __syncthreads();
    for (int o = 128; o > 0; o >>= 1) {
        if (t < o) { ss[t] += ss[t + o]; sq[t] += sq[t + o]; }
        __syncthreads();
    }
    if (t == 0) {
        float m = ss[0] / (float)B_ROWS;
        float v = sq[0] / (float)B_ROWS - m * m;
        float a = g[c] * rsqrtf(v + BN_EPS);
        g_a2[c] = a; g_cs2[c] = b[c] - m * a;
    }
}

// ---------------- shared GEMM machinery (f32x2) ----------------
#define DECL_ROW(I) unsigned long long c##I##0 = 0ull, c##I##1 = 0ull, c##I##2 = 0ull, c##I##3 = 0ull;

#define ROWFMA(I, AF) { \
    unsigned long long pa; \
    PACK2(pa, AF); \
    FMA2(c##I##0, pa, pb0); \
    FMA2(c##I##1, pa, pb1); \
    FMA2(c##I##2, pa, pb2); \
    FMA2(c##I##3, pa, pb3); }

#define KSTEP(KK) { \
    float4 a0 = *(const float4*)&As[KK][ty * 8]; \
    float4 a1 = *(const float4*)&As[KK][ty * 8 + 4]; \
    ulonglong2 bA = *(const ulonglong2*)&Bs[KK][tx * 8]; \
    ulonglong2 bB = *(const ulonglong2*)&Bs[KK][tx * 8 + 4]; \
    unsigned long long pb0 = bA.x, pb1 = bA.y, pb2 = bB.x, pb3 = bB.y; \
    ROWFMA(0, a0.x) ROWFMA(1, a0.y) ROWFMA(2, a0.z) ROWFMA(3, a0.w) \
    ROWFMA(4, a1.x) ROWFMA(5, a1.y) ROWFMA(6, a1.z) ROWFMA(7, a1.w) }

// ---------------- GEMM2: h2 = relu(Wg-dot(x)+cg) @ w2, bn2 partials ----------------
#define ROW2(I) { \
    float f0, f1, f2, f3, f4, f5, f6, f7; \
    UNPK(c##I##0, f0, f1) UNPK(c##I##1, f2, f3) UNPK(c##I##2, f4, f5) UNPK(c##I##3, f6, f7) \
    long r = row0 + ty * 8 + I; \
    *(float4*)&g_h2[r * HID + col0 + tx * 8]     = make_float4(f0, f1, f2, f3); \
    *(float4*)&g_h2[r * HID + col0 + tx * 8 + 4] = make_float4(f4, f5, f6, f7); \
    s0 += f0; s1 += f1; s2 += f2; s3 += f3; s4 += f4; s5 += f5; s6 += f6; s7 += f7; \
    q0 += f0*f0; q1 += f1*f1; q2 += f2*f2; q3 += f3*f3; \
    q4 += f4*f4; q5 += f5*f5; q6 += f6*f6; q7 += f7*f7; }

__global__ void __launch_bounds__(256) k_gemm2(const float* __restrict__ w2, const float* __restrict__ x) {
    __shared__ __align__(16) float As[8][132];
    __shared__ __align__(16) float Bs[8][132];
    __shared__ __align__(16) float xs[128][8];
    __shared__ __align__(16) float Wgs[8][HID];
    __shared__ __align__(16) float cgs[HID];
    __shared__ float red[16][128];
    int t = threadIdx.x;
    int tx = t & 15, ty = t >> 4;
    long row0 = (long)blockIdx.y * 128;
    int col0 = blockIdx.x * 128;
    for (int e = t; e < 1024; e += 256) {
        int r = e >> 3, p = e & 7;
        xs[r][p] = x[(row0 + r) * XCOLS + p];
    }
    for (int e = t; e < 2048; e += 256) Wgs[e >> 8][e & 255] = g_W1p[e];
    cgs[t] = g_c1[t];
    DECL_ROW(0) DECL_ROW(1) DECL_ROW(2) DECL_ROW(3)
    DECL_ROW(4) DECL_ROW(5) DECL_ROW(6) DECL_ROW(7)
    int bc = t & 127, bk = t >> 7;
    int kp = (t & 3) * 2, cr = t >> 2;
    __syncthreads();
    for (int k0 = 0; k0 < 256; k0 += 8) {
        #pragma unroll
        for (int i = 0; i < 2; i++) {
            int r = cr + i * 64;
            unsigned long long acc = *(const unsigned long long*)&cgs[k0 + kp];
            #pragma unroll
            for (int p = 0; p < 8; p++) {
                unsigned long long wv = *(const unsigned long long*)&Wgs[p][k0 + kp];
                unsigned long long xv;
                PACK2(xv, xs[r][p]);
                FMA2(acc, xv, wv);
            }
            float f0, f1;
            UNPK(acc, f0, f1)
            As[kp][r]     = fmaxf(f0, 0.f);
            As[kp + 1][r] = fmaxf(f1, 0.f);
        }
        #pragma unroll
        for (int i = 0; i < 4; i++) {
            int k = bk + i * 2;
            Bs[k][bc] = w2[(k0 + k) * HID + col0 + bc];
        }
        __syncthreads();
        #pragma unroll
        for (int k = 0; k < 8; k++) KSTEP(k)
        __syncthreads();
    }
    float s0 = 0.f, s1 = 0.f, s2 = 0.f, s3 = 0.f, s4 = 0.f, s5 = 0.f, s6 = 0.f, s7 = 0.f;
    float q0 = 0.f, q1 = 0.f, q2 = 0.f, q3 = 0.f, q4 = 0.f, q5 = 0.f, q6 = 0.f, q7 = 0.f;
    ROW2(0) ROW2(1) ROW2(2) ROW2(3) ROW2(4) ROW2(5) ROW2(6) ROW2(7)
    red[ty][tx * 8 + 0] = s0; red[ty][tx * 8 + 1] = s1;
    red[ty][tx * 8 + 2] = s2; red[ty][tx * 8 + 3] = s3;
    red[ty][tx * 8 + 4] = s4; red[ty][tx * 8 + 5] = s5;
    red[ty][tx * 8 + 6] = s6; red[ty][tx * 8 + 7] = s7;
    __syncthreads();
    if (t < 128) {
        float S = 0.f;
        #pragma unroll
        for (int y = 0; y < 16; y++) S += red[y][t];
        g_ps2[(long)(col0 + t) * 1024 + blockIdx.y] = S;
    }
    __syncthreads();
    red[ty][tx * 8 + 0] = q0; red[ty][tx * 8 + 1] = q1;
    red[ty][tx * 8 + 2] = q2; red[ty][tx * 8 + 3] = q3;
    red[ty][tx * 8 + 4] = q4; red[ty][tx * 8 + 5] = q5;
    red[ty][tx * 8 + 6] = q6; red[ty][tx * 8 + 7] = q7;
    __syncthreads();
    if (t < 128) {
        float Q = 0.f;
        #pragma unroll
        for (int y = 0; y < 16; y++) Q += red[y][t];
        g_pq2[(long)(col0 + t) * 1024 + blockIdx.y] = Q;
    }
}

// ---------------- GEMM3: 128x128 main tile + 2 fused remainder cols/block ----------------
#define ROW3(I) { \
    float f0, f1, f2, f3, f4, f5, f6, f7; \
    UNPK(c##I##0, f0, f1) UNPK(c##I##1, f2, f3) UNPK(c##I##2, f4, f5) UNPK(c##I##3, f6, f7) \
    long r = row0 + ty * 8 + I; \
    *(float4*)&g_Z[r * OUTC + c0]     = make_float4(f0 + bb0.x, f1 + bb0.y, f2 + bb0.z, f3 + bb0.w); \
    *(float4*)&g_Z[r * OUTC + c0 + 4] = make_float4(f4 + bb1.x, f5 + bb1.y, f6 + bb1.z, f7 + bb1.w); }

__global__ void __launch_bounds__(256) k_gemm3(const float* __restrict__ w3, const float* __restrict__ b3) {
    __shared__ __align__(16) float As[8][132];
    __shared__ __align__(16) float Bs[8][132];
    __shared__ float Wr[256][2];
    __shared__ float a2s[HID], cs2s[HID];
    int t = threadIdx.x;
    int tx = t & 15, ty = t >> 4;
    long row0 = (long)blockIdx.y * 128;
    int col0 = blockIdx.x * 128;
    int ce = 512 + blockIdx.x * 2;       // this block's 2 remainder cols
    a2s[t]  = g_a2[t];
    cs2s[t] = g_cs2[t];
    for (int e = t; e < 512; e += 256) {
        int k = e >> 1, c = e & 1;
        Wr[k][c] = w3[(long)k * OUTC + ce + c];
    }
    DECL_ROW(0) DECL_ROW(1) DECL_ROW(2) DECL_ROW(3)
    DECL_ROW(4) DECL_ROW(5) DECL_ROW(6) DECL_ROW(7)
    float eacc = 0.f;
    int er = t >> 1, ec = t & 1;         // thread owns (row er, remainder col ce+ec)
    int ar = t >> 3, ak = t & 7;
    int bc = t & 127, bk = t >> 7;
    __syncthreads();
    for (int k0 = 0; k0 < 256; k0 += 8) {
        #pragma unroll
        for (int i = 0; i < 4; i++) {
            int r = ar + i * 32;
            float h = g_h2[(row0 + r) * HID + k0 + ak];
            As[ak][r] = fmaxf(a2s[k0 + ak] * h + cs2s[k0 + ak], 0.f);
        }
        #pragma unroll
        for (int i = 0; i < 4; i++) {
            int k = bk + i * 2;
            Bs[k][bc] = w3[(long)(k0 + k) * OUTC + col0 + bc];
        }
        __syncthreads();
        #pragma unroll
        for (int k = 0; k < 8; k++) KSTEP(k)
        #pragma unroll
        for (int kk = 0; kk < 8; kk++)
            eacc += As[kk][er] * Wr[k0 + kk][ec];
        __syncthreads();
    }
    int c0 = col0 + tx * 8;
    float4 bb0 = *(const float4*)&b3[c0];
    float4 bb1 = *(const float4*)&b3[c0 + 4];
    ROW3(0) ROW3(1) ROW3(2) ROW3(3) ROW3(4) ROW3(5) ROW3(6) ROW3(7)
    g_Z[(row0 + er) * OUTC + ce + ec] = eacc + b3[ce + ec];
}

// ---------------- spline ----------------
__global__ void __launch_bounds__(128) k_spline(const float* __restrict__ x, float* __restrict__ out) {
    __shared__ float Zs[16 * OUTC];
    __shared__ float jf[16][8];
    int t = threadIdx.x;
    long row0 = (long)blockIdx.x * 16;
    for (int e = t; e < 16 * OUTC; e += 128) Zs[e] = g_Z[row0 * OUTC + e];
    __syncthreads();
    int r = t >> 3, tt = t & 7;
    long row = row0 + r;
    const float* z = &Zs[r * OUTC + tt * 65];

    float V[33], W[32];
    float Wn = 0.f;
    #pragma unroll
    for (int k = 0; k < 32; k++) { W[k] = __expf(z[33 + k]); Wn += W[k]; }
    #pragma unroll
    for (int k = 0; k < 33; k++) V[k] = __expf(z[k]);
    float Ttz = 0.f;
    #pragma unroll
    for (int k = 0; k < 32; k++) Ttz += (V[k] + V[k + 1]) * 0.5f * W[k];

    float xB = fminf(x[row * XCOLS + 8 + tt], 1.f - 1e-6f);
    float invWn = 1.f / Wn;

    float cw = 0.f, cvw = 0.f;
    float pre = 0.f, preV = 0.f;
    float Wj = W[31], Vj = V[31], Vj1 = V[32];
    bool found = false;
    #pragma unroll
    for (int k = 0; k < 32; k++) {
        float nw = cw + W[k];
        float post = nw * invWn;
        if (!found && post > xB) {
            found = true;
            pre = cw; preV = cvw;
            Wj = W[k]; Vj = V[k]; Vj1 = V[k + 1];
        }
        cw = nw;
        cvw += (V[k] + V[k + 1]) * 0.5f * W[k];
    }
    if (!found) {
        pre  = cw  - W[31];
        preV = cvw - (V[31] + V[32]) * 0.5f * W[31];
    }

    float invT  = 1.f / Ttz;
    float alpha = (xB * Wn - pre) / Wj;
    float shift = preV * invT;
    float VjN  = Vj  * Wn * invT;
    float Vj1N = Vj1 * Wn * invT;
    float WjN  = Wj * invWn;
    float yB = (0.5f * alpha * alpha * (Vj1N - VjN) + alpha * VjN) * WjN + shift;

    out[row * XCOLS + 8 + tt] = yB;
    out[row * XCOLS + tt]     = x[row * XCOLS + tt];
    jf[r][tt] = VjN + alpha * (Vj1N - VjN);
    __syncthreads();
    if (tt == 0) {
        float jac = x[row * XCOLS + 16];
        #pragma unroll
        for (int q = 0; q < 8; q++) jac *= jf[r][q];
        out[row * XCOLS + 16] = jac;
    }
}

// ---------------- launch ----------------
extern "C" void kernel_launch(void* const* d_in, const int* in_sizes, int n_in,
                              void* d_out, int out_size) {
    const float* x   = (const float*)d_in[0];
    const float* g0  = (const float*)d_in[1];
    const float* b0  = (const float*)d_in[2];
    const float* w1  = (const float*)d_in[3];
    const float* g1  = (const float*)d_in[4];
    const float* b1  = (const float*)d_in[5];
    const float* w2  = (const float*)d_in[6];
    const float* g2  = (const float*)d_in[7];
    const float* b2  = (const float*)d_in[8];
    const float* w3  = (const float*)d_in[9];
    const float* b3  = (const float*)d_in[10];
    float* out = (float*)d_out;

    k_stats_x2<<<128, 256>>>(x);
    k_prep1<<<1, 256>>>(g0, b0, w1, g1, b1);
    k_gemm2<<<dim3(2, 1024), 256>>>(w2, x);
    k_bnstats<<<256, 256>>>(g2, b2);
    k_gemm3<<<dim3(4, 1024), 256>>>(w3, b3);
    k_spline<<<8192, 128>>>(x, out);
}

// round 16
// speedup vs baseline: 1.0154x; 1.0069x over previous
#include <cuda_runtime.h>
#include <stdint.h>
#include <math.h>

#define B_ROWS 131072
#define PTS 8
#define XCOLS 17
#define HID 256
#define NBINS 32
#define OUTC 520
#define BN_EPS 1e-5f

// ---------------- static device scratch ----------------
__device__ float g_h2[(size_t)B_ROWS * HID];
__device__ float g_Z [(size_t)B_ROWS * OUTC];
__device__ float g_mom[44 * 128];
__device__ float g_ps2[HID * 1024];
__device__ float g_pq2[HID * 1024];
__device__ float g_W1p[PTS * HID];
__device__ float g_c1[HID];
__device__ float g_a2[HID], g_cs2[HID];

// ---------------- packed f32x2 helpers ----------------
#define FMA2(C, A, B) \
    asm("fma.rn.f32x2 %0, %1, %2, %0;" : "+l"(C) : "l"(A), "l"(B))
#define PACK2(P, F) \
    asm("mov.b64 %0, {%1, %1};" : "=l"(P) : "r"(__float_as_uint(F)))
#define UNPK(C, F0, F1) { \
    F0 = __uint_as_float((unsigned)(C)); \
    F1 = __uint_as_float((unsigned)((C) >> 32)); }

__host__ __device__ __forceinline__ int triidx(int p, int q) {
    return p * 8 - (p * (p - 1)) / 2 + (q - p);
}

// ---------------- moments of x[:, :8]: 8 sums + 36 cross sums ----------------
__global__ void k_stats_x2(const float* __restrict__ x) {
    __shared__ float wred[8][44];
    int t = threadIdx.x;
    int lane = t & 31, w = t >> 5;
    long base = (long)blockIdx.x * 1024;
    float s1[8], s2[36];
    #pragma unroll
    for (int p = 0; p < 8; p++) s1[p] = 0.f;
    #pragma unroll
    for (int i = 0; i < 36; i++) s2[i] = 0.f;
    for (int r = t; r < 1024; r += 256) {
        const float* xp = &x[(base + r) * XCOLS];
        float v[8];
        #pragma unroll
        for (int p = 0; p < 8; p++) v[p] = xp[p];
        #pragma unroll
        for (int p = 0; p < 8; p++) s1[p] += v[p];
        #pragma unroll
        for (int p = 0; p < 8; p++)
            #pragma unroll
            for (int q = p; q < 8; q++)
                s2[triidx(p, q)] += v[p] * v[q];
    }
    #pragma unroll
    for (int i = 0; i < 8; i++) {
        float v = s1[i];
        #pragma unroll
        for (int o = 16; o > 0; o >>= 1) v += __shfl_xor_sync(0xFFFFFFFFu, v, o);
        if (lane == 0) wred[w][i] = v;
    }
    #pragma unroll
    for (int i = 0; i < 36; i++) {
        float v = s2[i];
        #pragma unroll
        for (int o = 16; o > 0; o >>= 1) v += __shfl_xor_sync(0xFFFFFFFFu, v, o);
        if (lane == 0) wred[w][8 + i] = v;
    }
    __syncthreads();
    if (t < 44) {
        float S = 0.f;
        #pragma unroll
        for (int j = 0; j < 8; j++) S += wred[j][t];
        g_mom[t * 128 + blockIdx.x] = S;
    }
}

// ---------------- finalize bn0 + analytic bn1, fold into Wg/cg ----------------
__global__ void k_prep1(const float* __restrict__ g0, const float* __restrict__ b0,
                        const float* __restrict__ w1,
                        const float* __restrict__ g1, const float* __restrict__ b1) {
    __shared__ double mom[44];
    __shared__ double a0s[8], cs0s[8];
    __shared__ double m2s[8][8];
    int t = threadIdx.x;
    if (t < 44) {
        double S = 0.0;
        for (int j = 0; j < 128; j++) S += (double)g_mom[t * 128 + j];
        mom[t] = S / (double)B_ROWS;
    }
    __syncthreads();
    if (t < 8) {
        double m = mom[t];
        double v = mom[8 + triidx(t, t)] - m * m;
        double a = (double)g0[t] / sqrt(v + (double)BN_EPS);
        a0s[t] = a;
        cs0s[t] = (double)b0[t] - m * a;
    }
    if (t >= 64 && t < 128) {
        int p = (t - 64) >> 3, q = (t - 64) & 7;
        int pl = p < q ? p : q, qh = p < q ? q : p;
        m2s[p][q] = mom[8 + triidx(pl, qh)];
    }
    __syncthreads();
    int j = t;
    double Wf[8];
    double c1f = 0.0;
    #pragma unroll
    for (int p = 0; p < 8; p++) {
        double w = (double)w1[p * HID + j];
        Wf[p] = w * a0s[p];
        c1f += cs0s[p] * w;
    }
    double mx = 0.0;
    #pragma unroll
    for (int p = 0; p < 8; p++) mx += mom[p] * Wf[p];
    double mean1 = mx + c1f;
    double eh2 = c1f * c1f + 2.0 * c1f * mx;
    #pragma unroll
    for (int p = 0; p < 8; p++)
        #pragma unroll
        for (int q = 0; q < 8; q++)
            eh2 += m2s[p][q] * Wf[p] * Wf[q];
    double var1 = eh2 - mean1 * mean1;
    double a1 = (double)g1[j] / sqrt(var1 + (double)BN_EPS);
    double cs1 = (double)b1[j] - mean1 * a1;
    #pragma unroll
    for (int p = 0; p < 8; p++) g_W1p[p * HID + j] = (float)(Wf[p] * a1);
    g_c1[j] = (float)(c1f * a1 + cs1);
}

// ---------------- BN2 stats finalize ----------------
__global__ void k_bnstats(const float* __restrict__ g, const float* __restrict__ b) {
    __shared__ float ss[256], sq[256];
    int t = threadIdx.x, c = blockIdx.x;
    float S = 0.f, Q = 0.f;
    for (int j = t; j < 1024; j += 256) { S += g_ps2[c * 1024 + j]; Q += g_pq2[c * 1024 + j]; }
    ss[t] = S; sq[t] = Q;
    __syncthreads();
    for (int o = 128; o > 0; o >>= 1) {
        if (t < o) { ss[t] += ss[t + o]; sq[t] += sq[t + o]; }
        __syncthreads();
    }
    if (t == 0) {
        float m = ss[0] / (float)B_ROWS;
        float v = sq[0] / (float)B_ROWS - m * m;
        float a = g[c] * rsqrtf(v + BN_EPS);
        g_a2[c] = a; g_cs2[c] = b[c] - m * a;
    }
}

// ---------------- shared GEMM machinery (f32x2) ----------------
#define DECL_ROW(I) unsigned long long c##I##0 = 0ull, c##I##1 = 0ull, c##I##2 = 0ull, c##I##3 = 0ull;

#define ROWFMA(I, AF) { \
    unsigned long long pa; \
    PACK2(pa, AF); \
    FMA2(c##I##0, pa, pb0); \
    FMA2(c##I##1, pa, pb1); \
    FMA2(c##I##2, pa, pb2); \
    FMA2(c##I##3, pa, pb3); }

#define KSTEP(KK) { \
    float4 a0 = *(const float4*)&As[KK][ty * 8]; \
    float4 a1 = *(const float4*)&As[KK][ty * 8 + 4]; \
    ulonglong2 bA = *(const ulonglong2*)&Bs[KK][tx * 8]; \
    ulonglong2 bB = *(const ulonglong2*)&Bs[KK][tx * 8 + 4]; \
    unsigned long long pb0 = bA.x, pb1 = bA.y, pb2 = bB.x, pb3 = bB.y; \
    ROWFMA(0, a0.x) ROWFMA(1, a0.y) ROWFMA(2, a0.z) ROWFMA(3, a0.w) \
    ROWFMA(4, a1.x) ROWFMA(5, a1.y) ROWFMA(6, a1.z) ROWFMA(7, a1.w) }

// ---------------- GEMM2: h2 = relu(Wg-dot(x)+cg) @ w2, bn2 partials ----------------
#define ROW2(I) { \
    float f0, f1, f2, f3, f4, f5, f6, f7; \
    UNPK(c##I##0, f0, f1) UNPK(c##I##1, f2, f3) UNPK(c##I##2, f4, f5) UNPK(c##I##3, f6, f7) \
    long r = row0 + ty * 8 + I; \
    *(float4*)&g_h2[r * HID + col0 + tx * 8]     = make_float4(f0, f1, f2, f3); \
    *(float4*)&g_h2[r * HID + col0 + tx * 8 + 4] = make_float4(f4, f5, f6, f7); \
    s0 += f0; s1 += f1; s2 += f2; s3 += f3; s4 += f4; s5 += f5; s6 += f6; s7 += f7; \
    q0 += f0*f0; q1 += f1*f1; q2 += f2*f2; q3 += f3*f3; \
    q4 += f4*f4; q5 += f5*f5; q6 += f6*f6; q7 += f7*f7; }

__global__ void __launch_bounds__(256) k_gemm2(const float* __restrict__ w2, const float* __restrict__ x) {
    __shared__ __align__(16) float As[8][132];
    __shared__ __align__(16) float Bs[8][132];
    __shared__ __align__(16) float xs[128][8];
    __shared__ __align__(16) float Wgs[8][HID];
    __shared__ __align__(16) float cgs[HID];
    __shared__ float red[16][128];
    int t = threadIdx.x;
    int tx = t & 15, ty = t >> 4;
    long row0 = (long)blockIdx.y * 128;
    int col0 = blockIdx.x * 128;
    for (int e = t; e < 1024; e += 256) {
        int r = e >> 3, p = e & 7;
        xs[r][p] = x[(row0 + r) * XCOLS + p];
    }
    for (int e = t; e < 2048; e += 256) Wgs[e >> 8][e & 255] = g_W1p[e];
    cgs[t] = g_c1[t];
    DECL_ROW(0) DECL_ROW(1) DECL_ROW(2) DECL_ROW(3)
    DECL_ROW(4) DECL_ROW(5) DECL_ROW(6) DECL_ROW(7)
    int bc = t & 127, bk = t >> 7;
    int kp = (t & 3) * 2, cr = t >> 2;
    __syncthreads();
    for (int k0 = 0; k0 < 256; k0 += 8) {
        #pragma unroll
        for (int i = 0; i < 2; i++) {
            int r = cr + i * 64;
            unsigned long long acc = *(const unsigned long long*)&cgs[k0 + kp];
            #pragma unroll
            for (int p = 0; p < 8; p++) {
                unsigned long long wv = *(const unsigned long long*)&Wgs[p][k0 + kp];
                unsigned long long xv;
                PACK2(xv, xs[r][p]);
                FMA2(acc, xv, wv);
            }
            float f0, f1;
            UNPK(acc, f0, f1)
            As[kp][r]     = fmaxf(f0, 0.f);
            As[kp + 1][r] = fmaxf(f1, 0.f);
        }
        #pragma unroll
        for (int i = 0; i < 4; i++) {
            int k = bk + i * 2;
            Bs[k][bc] = w2[(k0 + k) * HID + col0 + bc];
        }
        __syncthreads();
        #pragma unroll
        for (int k = 0; k < 8; k++) KSTEP(k)
        __syncthreads();
    }
    float s0 = 0.f, s1 = 0.f, s2 = 0.f, s3 = 0.f, s4 = 0.f, s5 = 0.f, s6 = 0.f, s7 = 0.f;
    float q0 = 0.f, q1 = 0.f, q2 = 0.f, q3 = 0.f, q4 = 0.f, q5 = 0.f, q6 = 0.f, q7 = 0.f;
    ROW2(0) ROW2(1) ROW2(2) ROW2(3) ROW2(4) ROW2(5) ROW2(6) ROW2(7)
    red[ty][tx * 8 + 0] = s0; red[ty][tx * 8 + 1] = s1;
    red[ty][tx * 8 + 2] = s2; red[ty][tx * 8 + 3] = s3;
    red[ty][tx * 8 + 4] = s4; red[ty][tx * 8 + 5] = s5;
    red[ty][tx * 8 + 6] = s6; red[ty][tx * 8 + 7] = s7;
    __syncthreads();
    if (t < 128) {
        float S = 0.f;
        #pragma unroll
        for (int y = 0; y < 16; y++) S += red[y][t];
        g_ps2[(long)(col0 + t) * 1024 + blockIdx.y] = S;
    }
    __syncthreads();
    red[ty][tx * 8 + 0] = q0; red[ty][tx * 8 + 1] = q1;
    red[ty][tx * 8 + 2] = q2; red[ty][tx * 8 + 3] = q3;
    red[ty][tx * 8 + 4] = q4; red[ty][tx * 8 + 5] = q5;
    red[ty][tx * 8 + 6] = q6; red[ty][tx * 8 + 7] = q7;
    __syncthreads();
    if (t < 128) {
        float Q = 0.f;
        #pragma unroll
        for (int y = 0; y < 16; y++) Q += red[y][t];
        g_pq2[(long)(col0 + t) * 1024 + blockIdx.y] = Q;
    }
}

// ---------------- GEMM3 main: cols 0..511 ----------------
#define ROW3(I) { \
    float f0, f1, f2, f3, f4, f5, f6, f7; \
    UNPK(c##I##0, f0, f1) UNPK(c##I##1, f2, f3) UNPK(c##I##2, f4, f5) UNPK(c##I##3, f6, f7) \
    long r = row0 + ty * 8 + I; \
    *(float4*)&g_Z[r * OUTC + c0]     = make_float4(f0 + bb0.x, f1 + bb0.y, f2 + bb0.z, f3 + bb0.w); \
    *(float4*)&g_Z[r * OUTC + c0 + 4] = make_float4(f4 + bb1.x, f5 + bb1.y, f6 + bb1.z, f7 + bb1.w); }

__global__ void __launch_bounds__(256) k_gemm3(const float* __restrict__ w3, const float* __restrict__ b3) {
    __shared__ __align__(16) float As[8][132];
    __shared__ __align__(16) float Bs[8][132];
    __shared__ float a2s[HID], cs2s[HID];
    int t = threadIdx.x;
    int tx = t & 15, ty = t >> 4;
    long row0 = (long)blockIdx.y * 128;
    int col0 = blockIdx.x * 128;
    a2s[t]  = g_a2[t];
    cs2s[t] = g_cs2[t];
    DECL_ROW(0) DECL_ROW(1) DECL_ROW(2) DECL_ROW(3)
    DECL_ROW(4) DECL_ROW(5) DECL_ROW(6) DECL_ROW(7)
    int ar = t >> 3, ak = t & 7;
    int bc = t & 127, bk = t >> 7;
    __syncthreads();
    for (int k0 = 0; k0 < 256; k0 += 8) {
        #pragma unroll
        for (int i = 0; i < 4; i++) {
            int r = ar + i * 32;
            float h = g_h2[(row0 + r) * HID + k0 + ak];
            As[ak][r] = fmaxf(a2s[k0 + ak] * h + cs2s[k0 + ak], 0.f);
        }
        #pragma unroll
        for (int i = 0; i < 4; i++) {
            int k = bk + i * 2;
            Bs[k][bc] = w3[(long)(k0 + k) * OUTC + col0 + bc];
        }
        __syncthreads();
        #pragma unroll
        for (int k = 0; k < 8; k++) KSTEP(k)
        __syncthreads();
    }
    int c0 = col0 + tx * 8;
    float4 bb0 = *(const float4*)&b3[c0];
    float4 bb1 = *(const float4*)&b3[c0 + 4];
    ROW3(0) ROW3(1) ROW3(2) ROW3(3) ROW3(4) ROW3(5) ROW3(6) ROW3(7)
}

// ---------------- GEMM3 remainder: cols 512..519 ----------------
__global__ void __launch_bounds__(256) k_gemm3r(const float* __restrict__ w3, const float* __restrict__ b3) {
    __shared__ float Ws[256][8];
    __shared__ __align__(16) float As[8][132];
    __shared__ float a2s[HID], cs2s[HID];
    int t = threadIdx.x;
    long row0 = (long)blockIdx.x * 128;
    a2s[t]  = g_a2[t];
    cs2s[t] = g_cs2[t];
    #pragma unroll
    for (int e = 0; e < 8; e++) {
        int idx = t + e * 256;
        int k = idx >> 3, c = idx & 7;
        Ws[k][c] = w3[(long)k * OUTC + 512 + c];
    }
    __syncthreads();
    int c = t & 7, rg = t >> 3;
    int ar = t >> 3, ak = t & 7;
    float bb = b3[512 + c];
    float ac0 = bb, ac1 = bb, ac2 = bb, ac3 = bb;
    for (int k0 = 0; k0 < 256; k0 += 8) {
        if (k0) __syncthreads();
        #pragma unroll
        for (int i = 0; i < 4; i++) {
            int r = ar + i * 32;
            float h = g_h2[(row0 + r) * HID + k0 + ak];
            As[ak][r] = fmaxf(a2s[k0 + ak] * h + cs2s[k0 + ak], 0.f);
        }
        __syncthreads();
        #pragma unroll
        for (int kk = 0; kk < 8; kk++) {
            float w = Ws[k0 + kk][c];
            float4 av = *(const float4*)&As[kk][rg * 4];
            ac0 += av.x * w;
            ac1 += av.y * w;
            ac2 += av.z * w;
            ac3 += av.w * w;
        }
    }
    long r = row0 + rg * 4;
    g_Z[r * OUTC + 512 + c]       = ac0;
    g_Z[(r + 1) * OUTC + 512 + c] = ac1;
    g_Z[(r + 2) * OUTC + 512 + c] = ac2;
    g_Z[(r + 3) * OUTC + 512 + c] = ac3;
}

// ---------------- spline (rows processed in DESCENDING order for L2 reuse) ----------------
__global__ void __launch_bounds__(128) k_spline(const float* __restrict__ x, float* __restrict__ out) {
    __shared__ float Zs[16 * OUTC];
    __shared__ float jf[16][8];
    int t = threadIdx.x;
    long row0 = (long)(gridDim.x - 1 - blockIdx.x) * 16;
    for (int e = t; e < 16 * OUTC; e += 128) Zs[e] = g_Z[row0 * OUTC + e];
    __syncthreads();
    int r = t >> 3, tt = t & 7;
    long row = row0 + r;
    const float* z = &Zs[r * OUTC + tt * 65];

    float V[33], W[32];
    float Wn = 0.f;
    #pragma unroll
    for (int k = 0; k < 32; k++) { W[k] = __expf(z[33 + k]); Wn += W[k]; }
    #pragma unroll
    for (int k = 0; k < 33; k++) V[k] = __expf(z[k]);
    float Ttz = 0.f;
    #pragma unroll
    for (int k = 0; k < 32; k++) Ttz += (V[k] + V[k + 1]) * 0.5f * W[k];

    float xB = fminf(x[row * XCOLS + 8 + tt], 1.f - 1e-6f);
    float invWn = 1.f / Wn;

    float cw = 0.f, cvw = 0.f;
    float pre = 0.f, preV = 0.f;
    float Wj = W[31], Vj = V[31], Vj1 = V[32];
    bool found = false;
    #pragma unroll
    for (int k = 0; k < 32; k++) {
        float nw = cw + W[k];
        float post = nw * invWn;
        if (!found && post > xB) {
            found = true;
            pre = cw; preV = cvw;
            Wj = W[k]; Vj = V[k]; Vj1 = V[k + 1];
        }
        cw = nw;
        cvw += (V[k] + V[k + 1]) * 0.5f * W[k];
    }
    if (!found) {
        pre  = cw  - W[31];
        preV = cvw - (V[31] + V[32]) * 0.5f * W[31];
    }

    float invT  = 1.f / Ttz;
    float alpha = (xB * Wn - pre) / Wj;
    float shift = preV * invT;
    float VjN  = Vj  * Wn * invT;
    float Vj1N = Vj1 * Wn * invT;
    float WjN  = Wj * invWn;
    float yB = (0.5f * alpha * alpha * (Vj1N - VjN) + alpha * VjN) * WjN + shift;

    out[row * XCOLS + 8 + tt] = yB;
    out[row * XCOLS + tt]     = x[row * XCOLS + tt];
    jf[r][tt] = VjN + alpha * (Vj1N - VjN);
    __syncthreads();
    if (tt == 0) {
        float jac = x[row * XCOLS + 16];
        #pragma unroll
        for (int q = 0; q < 8; q++) jac *= jf[r][q];
        out[row * XCOLS + 16] = jac;
    }
}

// ---------------- launch ----------------
extern "C" void kernel_launch(void* const* d_in, const int* in_sizes, int n_in,
                              void* d_out, int out_size) {
    const float* x   = (const float*)d_in[0];
    const float* g0  = (const float*)d_in[1];
    const float* b0  = (const float*)d_in[2];
    const float* w1  = (const float*)d_in[3];
    const float* g1  = (const float*)d_in[4];
    const float* b1  = (const float*)d_in[5];
    const float* w2  = (const float*)d_in[6];
    const float* g2  = (const float*)d_in[7];
    const float* b2  = (const float*)d_in[8];
    const float* w3  = (const float*)d_in[9];
    const float* b3  = (const float*)d_in[10];
    float* out = (float*)d_out;

    k_stats_x2<<<128, 256>>>(x);
    k_prep1<<<1, 256>>>(g0, b0, w1, g1, b1);
    k_gemm2<<<dim3(2, 1024), 256>>>(w2, x);
    k_bnstats<<<256, 256>>>(g2, b2);
    k_gemm3<<<dim3(4, 1024), 256>>>(w3, b3);
    k_gemm3r<<<1024, 256>>>(w3, b3);
    k_spline<<<8192, 128>>>(x, out);
}

// round 17
// speedup vs baseline: 1.0159x; 1.0005x over previous
#include <cuda_runtime.h>
#include <stdint.h>
#include <math.h>

#define B_ROWS 131072
#define PTS 8
#define XCOLS 17
#define HID 256
#define NBINS 32
#define OUTC 520
#define BN_EPS 1e-5f

// ---------------- static device scratch ----------------
__device__ float g_h2[(size_t)B_ROWS * HID];
__device__ float g_Z [(size_t)B_ROWS * OUTC];
__device__ float g_mom[44 * 128];
__device__ float g_ps2[HID * 1024];
__device__ float g_pq2[HID * 1024];
__device__ float g_W1p[PTS * HID];
__device__ float g_c1[HID];
__device__ float g_a2[HID], g_cs2[HID];

// ---------------- packed f32x2 helpers ----------------
#define FMA2(C, A, B) \
    asm("fma.rn.f32x2 %0, %1, %2, %0;" : "+l"(C) : "l"(A), "l"(B))
#define PACK2(P, F) \
    asm("mov.b64 %0, {%1, %1};" : "=l"(P) : "r"(__float_as_uint(F)))
#define UNPK(C, F0, F1) { \
    F0 = __uint_as_float((unsigned)(C)); \
    F1 = __uint_as_float((unsigned)((C) >> 32)); }

__host__ __device__ __forceinline__ int triidx(int p, int q) {
    return p * 8 - (p * (p - 1)) / 2 + (q - p);
}

// ---------------- moments of x[:, :8]: 8 sums + 36 cross sums ----------------
__global__ void k_stats_x2(const float* __restrict__ x) {
    __shared__ float wred[8][44];
    int t = threadIdx.x;
    int lane = t & 31, w = t >> 5;
    long base = (long)blockIdx.x * 1024;
    float s1[8], s2[36];
    #pragma unroll
    for (int p = 0; p < 8; p++) s1[p] = 0.f;
    #pragma unroll
    for (int i = 0; i < 36; i++) s2[i] = 0.f;
    for (int r = t; r < 1024; r += 256) {
        const float* xp = &x[(base + r) * XCOLS];
        float v[8];
        #pragma unroll
        for (int p = 0; p < 8; p++) v[p] = xp[p];
        #pragma unroll
        for (int p = 0; p < 8; p++) s1[p] += v[p];
        #pragma unroll
        for (int p = 0; p < 8; p++)
            #pragma unroll
            for (int q = p; q < 8; q++)
                s2[triidx(p, q)] += v[p] * v[q];
    }
    #pragma unroll
    for (int i = 0; i < 8; i++) {
        float v = s1[i];
        #pragma unroll
        for (int o = 16; o > 0; o >>= 1) v += __shfl_xor_sync(0xFFFFFFFFu, v, o);
        if (lane == 0) wred[w][i] = v;
    }
    #pragma unroll
    for (int i = 0; i < 36; i++) {
        float v = s2[i];
        #pragma unroll
        for (int o = 16; o > 0; o >>= 1) v += __shfl_xor_sync(0xFFFFFFFFu, v, o);
        if (lane == 0) wred[w][8 + i] = v;
    }
    __syncthreads();
    if (t < 44) {
        float S = 0.f;
        #pragma unroll
        for (int j = 0; j < 8; j++) S += wred[j][t];
        g_mom[t * 128 + blockIdx.x] = S;
    }
}

// ---------------- finalize bn0 + analytic bn1, fold into Wg/cg ----------------
__global__ void k_prep1(const float* __restrict__ g0, const float* __restrict__ b0,
                        const float* __restrict__ w1,
                        const float* __restrict__ g1, const float* __restrict__ b1) {
    __shared__ double mom[44];
    __shared__ double a0s[8], cs0s[8];
    __shared__ double m2s[8][8];
    int t = threadIdx.x;
    if (t < 44) {
        double S = 0.0;
        for (int j = 0; j < 128; j++) S += (double)g_mom[t * 128 + j];
        mom[t] = S / (double)B_ROWS;
    }
    __syncthreads();
    if (t < 8) {
        double m = mom[t];
        double v = mom[8 + triidx(t, t)] - m * m;
        double a = (double)g0[t] / sqrt(v + (double)BN_EPS);
        a0s[t] = a;
        cs0s[t] = (double)b0[t] - m * a;
    }
    if (t >= 64 && t < 128) {
        int p = (t - 64) >> 3, q = (t - 64) & 7;
        int pl = p < q ? p : q, qh = p < q ? q : p;
        m2s[p][q] = mom[8 + triidx(pl, qh)];
    }
    __syncthreads();
    int j = t;
    double Wf[8];
    double c1f = 0.0;
    #pragma unroll
    for (int p = 0; p < 8; p++) {
        double w = (double)w1[p * HID + j];
        Wf[p] = w * a0s[p];
        c1f += cs0s[p] * w;
    }
    double mx = 0.0;
    #pragma unroll
    for (int p = 0; p < 8; p++) mx += mom[p] * Wf[p];
    double mean1 = mx + c1f;
    double eh2 = c1f * c1f + 2.0 * c1f * mx;
    #pragma unroll
    for (int p = 0; p < 8; p++)
        #pragma unroll
        for (int q = 0; q < 8; q++)
            eh2 += m2s[p][q] * Wf[p] * Wf[q];
    double var1 = eh2 - mean1 * mean1;
    double a1 = (double)g1[j] / sqrt(var1 + (double)BN_EPS);
    double cs1 = (double)b1[j] - mean1 * a1;
    #pragma unroll
    for (int p = 0; p < 8; p++) g_W1p[p * HID + j] = (float)(Wf[p] * a1);
    g_c1[j] = (float)(c1f * a1 + cs1);
}

// ---------------- BN2 stats finalize ----------------
__global__ void k_bnstats(const float* __restrict__ g, const float* __restrict__ b) {
    __shared__ float ss[256], sq[256];
    int t = threadIdx.x, c = blockIdx.x;
    float S = 0.f, Q = 0.f;
    for (int j = t; j < 1024; j += 256) { S += g_ps2[c * 1024 + j]; Q += g_pq2[c * 1024 + j]; }
    ss[t] = S; sq[t] = Q;
    __syncthreads();
    for (int o = 128; o > 0; o >>= 1) {
        if (t < o) { ss[t] += ss[t + o]; sq[t] += sq[t + o]; }
        __syncthreads();
    }
    if (t == 0) {
        float m = ss[0] / (float)B_ROWS;
        float v = sq[0] / (float)B_ROWS - m * m;
        float a = g[c] * rsqrtf(v + BN_EPS);
        g_a2[c] = a; g_cs2[c] = b[c] - m * a;
    }
}

// ---------------- shared GEMM machinery (f32x2) ----------------
#define DECL_ROW(I) unsigned long long c##I##0 = 0ull, c##I##1 = 0ull, c##I##2 = 0ull, c##I##3 = 0ull;

#define ROWFMA(I, AF) { \
    unsigned long long pa; \
    PACK2(pa, AF); \
    FMA2(c##I##0, pa, pb0); \
    FMA2(c##I##1, pa, pb1); \
    FMA2(c##I##2, pa, pb2); \
    FMA2(c##I##3, pa, pb3); }

#define KSTEP(KK) { \
    float4 a0 = *(const float4*)&As[KK][ty * 8]; \
    float4 a1 = *(const float4*)&As[KK][ty * 8 + 4]; \
    ulonglong2 bA = *(const ulonglong2*)&Bs[KK][tx * 8]; \
    ulonglong2 bB = *(const ulonglong2*)&Bs[KK][tx * 8 + 4]; \
    unsigned long long pb0 = bA.x, pb1 = bA.y, pb2 = bB.x, pb3 = bB.y; \
    ROWFMA(0, a0.x) ROWFMA(1, a0.y) ROWFMA(2, a0.z) ROWFMA(3, a0.w) \
    ROWFMA(4, a1.x) ROWFMA(5, a1.y) ROWFMA(6, a1.z) ROWFMA(7, a1.w) }

// ---------------- GEMM2: h2 = relu(Wg-dot(x)+cg) @ w2, bn2 partials ----------------
#define ROW2(I) { \
    float f0, f1, f2, f3, f4, f5, f6, f7; \
    UNPK(c##I##0, f0, f1) UNPK(c##I##1, f2, f3) UNPK(c##I##2, f4, f5) UNPK(c##I##3, f6, f7) \
    long r = row0 + ty * 8 + I; \
    *(float4*)&g_h2[r * HID + col0 + tx * 8]     = make_float4(f0, f1, f2, f3); \
    *(float4*)&g_h2[r * HID + col0 + tx * 8 + 4] = make_float4(f4, f5, f6, f7); \
    s0 += f0; s1 += f1; s2 += f2; s3 += f3; s4 += f4; s5 += f5; s6 += f6; s7 += f7; \
    q0 += f0*f0; q1 += f1*f1; q2 += f2*f2; q3 += f3*f3; \
    q4 += f4*f4; q5 += f5*f5; q6 += f6*f6; q7 += f7*f7; }

__global__ void __launch_bounds__(256) k_gemm2(const float* __restrict__ w2, const float* __restrict__ x) {
    __shared__ __align__(16) float As[8][132];
    __shared__ __align__(16) float Bs[8][132];
    __shared__ __align__(16) float xs[128][8];
    __shared__ __align__(16) float Wgs[8][HID];
    __shared__ __align__(16) float cgs[HID];
    __shared__ float red[16][128];
    int t = threadIdx.x;
    int tx = t & 15, ty = t >> 4;
    long row0 = (long)blockIdx.y * 128;
    int col0 = blockIdx.x * 128;
    for (int e = t; e < 1024; e += 256) {
        int r = e >> 3, p = e & 7;
        xs[r][p] = x[(row0 + r) * XCOLS + p];
    }
    for (int e = t; e < 2048; e += 256) Wgs[e >> 8][e & 255] = g_W1p[e];
    cgs[t] = g_c1[t];
    DECL_ROW(0) DECL_ROW(1) DECL_ROW(2) DECL_ROW(3)
    DECL_ROW(4) DECL_ROW(5) DECL_ROW(6) DECL_ROW(7)
    int bc = t & 127, bk = t >> 7;
    int kp = (t & 3) * 2, cr = t >> 2;
    __syncthreads();
    for (int k0 = 0; k0 < 256; k0 += 8) {
        #pragma unroll
        for (int i = 0; i < 2; i++) {
            int r = cr + i * 64;
            unsigned long long acc = *(const unsigned long long*)&cgs[k0 + kp];
            #pragma unroll
            for (int p = 0; p < 8; p++) {
                unsigned long long wv = *(const unsigned long long*)&Wgs[p][k0 + kp];
                unsigned long long xv;
                PACK2(xv, xs[r][p]);
                FMA2(acc, xv, wv);
            }
            float f0, f1;
            UNPK(acc, f0, f1)
            As[kp][r]     = fmaxf(f0, 0.f);
            As[kp + 1][r] = fmaxf(f1, 0.f);
        }
        #pragma unroll
        for (int i = 0; i < 4; i++) {
            int k = bk + i * 2;
            Bs[k][bc] = w2[(k0 + k) * HID + col0 + bc];
        }
        __syncthreads();
        #pragma unroll
        for (int k = 0; k < 8; k++) KSTEP(k)
        __syncthreads();
    }
    float s0 = 0.f, s1 = 0.f, s2 = 0.f, s3 = 0.f, s4 = 0.f, s5 = 0.f, s6 = 0.f, s7 = 0.f;
    float q0 = 0.f, q1 = 0.f, q2 = 0.f, q3 = 0.f, q4 = 0.f, q5 = 0.f, q6 = 0.f, q7 = 0.f;
    ROW2(0) ROW2(1) ROW2(2) ROW2(3) ROW2(4) ROW2(5) ROW2(6) ROW2(7)
    red[ty][tx * 8 + 0] = s0; red[ty][tx * 8 + 1] = s1;
    red[ty][tx * 8 + 2] = s2; red[ty][tx * 8 + 3] = s3;
    red[ty][tx * 8 + 4] = s4; red[ty][tx * 8 + 5] = s5;
    red[ty][tx * 8 + 6] = s6; red[ty][tx * 8 + 7] = s7;
    __syncthreads();
    if (t < 128) {
        float S = 0.f;
        #pragma unroll
        for (int y = 0; y < 16; y++) S += red[y][t];
        g_ps2[(long)(col0 + t) * 1024 + blockIdx.y] = S;
    }
    __syncthreads();
    red[ty][tx * 8 + 0] = q0; red[ty][tx * 8 + 1] = q1;
    red[ty][tx * 8 + 2] = q2; red[ty][tx * 8 + 3] = q3;
    red[ty][tx * 8 + 4] = q4; red[ty][tx * 8 + 5] = q5;
    red[ty][tx * 8 + 6] = q6; red[ty][tx * 8 + 7] = q7;
    __syncthreads();
    if (t < 128) {
        float Q = 0.f;
        #pragma unroll
        for (int y = 0; y < 16; y++) Q += red[y][t];
        g_pq2[(long)(col0 + t) * 1024 + blockIdx.y] = Q;
    }
}

// ---------------- GEMM3 main: cols 0..511 ----------------
#define ROW3(I) { \
    float f0, f1, f2, f3, f4, f5, f6, f7; \
    UNPK(c##I##0, f0, f1) UNPK(c##I##1, f2, f3) UNPK(c##I##2, f4, f5) UNPK(c##I##3, f6, f7) \
    long r = row0 + ty * 8 + I; \
    *(float4*)&g_Z[r * OUTC + c0]     = make_float4(f0 + bb0.x, f1 + bb0.y, f2 + bb0.z, f3 + bb0.w); \
    *(float4*)&g_Z[r * OUTC + c0 + 4] = make_float4(f4 + bb1.x, f5 + bb1.y, f6 + bb1.z, f7 + bb1.w); }

__global__ void __launch_bounds__(256) k_gemm3(const float* __restrict__ w3, const float* __restrict__ b3) {
    __shared__ __align__(16) float As[8][132];
    __shared__ __align__(16) float Bs[8][132];
    __shared__ float a2s[HID], cs2s[HID];
    int t = threadIdx.x;
    int tx = t & 15, ty = t >> 4;
    long row0 = (long)blockIdx.y * 128;
    int col0 = blockIdx.x * 128;
    a2s[t]  = g_a2[t];
    cs2s[t] = g_cs2[t];
    DECL_ROW(0) DECL_ROW(1) DECL_ROW(2) DECL_ROW(3)
    DECL_ROW(4) DECL_ROW(5) DECL_ROW(6) DECL_ROW(7)
    int ar = t >> 3, ak = t & 7;
    int bc = t & 127, bk = t >> 7;
    __syncthreads();
    for (int k0 = 0; k0 < 256; k0 += 8) {
        #pragma unroll
        for (int i = 0; i < 4; i++) {
            int r = ar + i * 32;
            float h = g_h2[(row0 + r) * HID + k0 + ak];
            As[ak][r] = fmaxf(a2s[k0 + ak] * h + cs2s[k0 + ak], 0.f);
        }
        #pragma unroll
        for (int i = 0; i < 4; i++) {
            int k = bk + i * 2;
            Bs[k][bc] = w3[(long)(k0 + k) * OUTC + col0 + bc];
        }
        __syncthreads();
        #pragma unroll
        for (int k = 0; k < 8; k++) KSTEP(k)
        __syncthreads();
    }
    int c0 = col0 + tx * 8;
    float4 bb0 = *(const float4*)&b3[c0];
    float4 bb1 = *(const float4*)&b3[c0 + 4];
    ROW3(0) ROW3(1) ROW3(2) ROW3(3) ROW3(4) ROW3(5) ROW3(6) ROW3(7)
}

// ---------------- GEMM3 remainder: cols 512..519 ----------------
__global__ void __launch_bounds__(256) k_gemm3r(const float* __restrict__ w3, const float* __restrict__ b3) {
    __shared__ float Ws[256][8];
    __shared__ __align__(16) float As[8][132];
    __shared__ float a2s[HID], cs2s[HID];
    int t = threadIdx.x;
    long row0 = (long)blockIdx.x * 128;
    a2s[t]  = g_a2[t];
    cs2s[t] = g_cs2[t];
    #pragma unroll
    for (int e = 0; e < 8; e++) {
        int idx = t + e * 256;
        int k = idx >> 3, c = idx & 7;
        Ws[k][c] = w3[(long)k * OUTC + 512 + c];
    }
    __syncthreads();
    int c = t & 7, rg = t >> 3;
    int ar = t >> 3, ak = t & 7;
    float bb = b3[512 + c];
    float ac0 = bb, ac1 = bb, ac2 = bb, ac3 = bb;
    for (int k0 = 0; k0 < 256; k0 += 8) {
        if (k0) __syncthreads();
        #pragma unroll
        for (int i = 0; i < 4; i++) {
            int r = ar + i * 32;
            float h = g_h2[(row0 + r) * HID + k0 + ak];
            As[ak][r] = fmaxf(a2s[k0 + ak] * h + cs2s[k0 + ak], 0.f);
        }
        __syncthreads();
        #pragma unroll
        for (int kk = 0; kk < 8; kk++) {
            float w = Ws[k0 + kk][c];
            float4 av = *(const float4*)&As[kk][rg * 4];
            ac0 += av.x * w;
            ac1 += av.y * w;
            ac2 += av.z * w;
            ac3 += av.w * w;
        }
    }
    long r = row0 + rg * 4;
    g_Z[r * OUTC + 512 + c]       = ac0;
    g_Z[(r + 1) * OUTC + 512 + c] = ac1;
    g_Z[(r + 2) * OUTC + 512 + c] = ac2;
    g_Z[(r + 3) * OUTC + 512 + c] = ac3;
}

// ---------------- spline (rows processed in DESCENDING order for L2 reuse) ----------------
__global__ void __launch_bounds__(128) k_spline(const float* __restrict__ x, float* __restrict__ out) {
    __shared__ float Zs[16 * OUTC];
    __shared__ float jf[16][8];
    int t = threadIdx.x;
    long row0 = (long)(gridDim.x - 1 - blockIdx.x) * 16;
    for (int e = t; e < 16 * OUTC; e += 128) Zs[e] = g_Z[row0 * OUTC + e];
    __syncthreads();
    int r = t >> 3, tt = t & 7;
    long row = row0 + r;
    const float* z = &Zs[r * OUTC + tt * 65];

    float V[33], W[32];
    float Wn = 0.f;
    #pragma unroll
    for (int k = 0; k < 32; k++) { W[k] = __expf(z[33 + k]); Wn += W[k]; }
    #pragma unroll
    for (int k = 0; k < 33; k++) V[k] = __expf(z[k]);
    float Ttz = 0.f;
    #pragma unroll
    for (int k = 0; k < 32; k++) Ttz += (V[k] + V[k + 1]) * 0.5f * W[k];

    float xB = fminf(x[row * XCOLS + 8 + tt], 1.f - 1e-6f);
    float invWn = 1.f / Wn;

    float cw = 0.f, cvw = 0.f;
    float pre = 0.f, preV = 0.f;
    float Wj = W[31], Vj = V[31], Vj1 = V[32];
    bool found = false;
    #pragma unroll
    for (int k = 0; k < 32; k++) {
        float nw = cw + W[k];
        float post = nw * invWn;
        if (!found && post > xB) {
            found = true;
            pre = cw; preV = cvw;
            Wj = W[k]; Vj = V[k]; Vj1 = V[k + 1];
        }
        cw = nw;
        cvw += (V[k] + V[k + 1]) * 0.5f * W[k];
    }
    if (!found) {
        pre  = cw  - W[31];
        preV = cvw - (V[31] + V[32]) * 0.5f * W[31];
    }

    float invT  = 1.f / Ttz;
    float alpha = (xB * Wn - pre) / Wj;
    float shift = preV * invT;
    float VjN  = Vj  * Wn * invT;
    float Vj1N = Vj1 * Wn * invT;
    float WjN  = Wj * invWn;
    float yB = (0.5f * alpha * alpha * (Vj1N - VjN) + alpha * VjN) * WjN + shift;

    out[row * XCOLS + 8 + tt] = yB;
    out[row * XCOLS + tt]     = x[row * XCOLS + tt];
    jf[r][tt] = VjN + alpha * (Vj1N - VjN);
    __syncthreads();
    if (tt == 0) {
        float jac = x[row * XCOLS + 16];
        #pragma unroll
        for (int q = 0; q < 8; q++) jac *= jf[r][q];
        out[row * XCOLS + 16] = jac;
    }
}

// ---------------- launch ----------------
extern "C" void kernel_launch(void* const* d_in, const int* in_sizes, int n_in,
                              void* d_out, int out_size) {
    const float* x   = (const float*)d_in[0];
    const float* g0  = (const float*)d_in[1];
    const float* b0  = (const float*)d_in[2];
    const float* w1  = (const float*)d_in[3];
    const float* g1  = (const float*)d_in[4];
    const float* b1  = (const float*)d_in[5];
    const float* w2  = (const float*)d_in[6];
    const float* g2  = (const float*)d_in[7];
    const float* b2  = (const float*)d_in[8];
    const float* w3  = (const float*)d_in[9];
    const float* b3  = (const float*)d_in[10];
    float* out = (float*)d_out;

    k_stats_x2<<<128, 256>>>(x);
    k_prep1<<<1, 256>>>(g0, b0, w1, g1, b1);
    k_gemm2<<<dim3(2, 1024), 256>>>(w2, x);
    k_bnstats<<<256, 256>>>(g2, b2);
    k_gemm3<<<dim3(4, 1024), 256>>>(w3, b3);
    k_gemm3r<<<1024, 256>>>(w3, b3);
    k_spline<<<8192, 128>>>(x, out);
}